// round 8
// baseline (speedup 1.0000x reference)
#include <cuda_runtime.h>

typedef unsigned long long ull;

#define BATCH 128
#define SEQ   4096
#define NPOS  (BATCH * SEQ)

// Scratch for the cumsum (temp_seq). __device__ global: no allocation.
__device__ float g_temp[NPOS];

// ---------------- packed f32x2 helpers ----------------
__device__ __forceinline__ ull pk(float a, float b) {
    ull r; asm("mov.b64 %0, {%1, %2};" : "=l"(r) : "f"(a), "f"(b)); return r;
}
__device__ __forceinline__ void upk(ull v, float& a, float& b) {
    asm("mov.b64 {%0, %1}, %2;" : "=f"(a), "=f"(b) : "l"(v));
}
__device__ __forceinline__ ull fma2(ull a, ull b, ull c) {
    ull r; asm("fma.rn.f32x2 %0, %1, %2, %3;" : "=l"(r) : "l"(a), "l"(b), "l"(c)); return r;
}
__device__ __forceinline__ ull add2(ull a, ull b) {
    ull r; asm("add.rn.f32x2 %0, %1, %2;" : "=l"(r) : "l"(a), "l"(b)); return r;
}

// Accurate tanh (scalar): tanh(x) = sign(x)*(1-e^{-2|x|})/(1+e^{-2|x|})
__device__ __forceinline__ float fast_tanh(float x) {
    float t = __expf(-2.0f * fabsf(x));
    float r = __fdividef(1.0f - t, 1.0f + t);
    return copysignf(r, x);
}

// Fused gated tanh on a packed position-pair:
// tanh(a)*tanh(b) = sign(a^b) * (1-ta)(1-tb) / ((1+ta)(1+tb)),  t = e^{-2|x|}
// One reciprocal per gate per position instead of two.
__device__ __forceinline__ ull gtanh2(ull a2, ull b2) {
    float a0, a1, b0, b1;
    upk(a2, a0, a1); upk(b2, b0, b1);
    float ta0 = __expf(-2.0f * fabsf(a0));
    float tb0 = __expf(-2.0f * fabsf(b0));
    float ta1 = __expf(-2.0f * fabsf(a1));
    float tb1 = __expf(-2.0f * fabsf(b1));
    float n0 = (1.0f - ta0) * (1.0f - tb0);
    float d0 = (1.0f + ta0) * (1.0f + tb0);
    float n1 = (1.0f - ta1) * (1.0f - tb1);
    float d1 = (1.0f + ta1) * (1.0f + tb1);
    float r0 = __fdividef(n0, d0);
    float r1 = __fdividef(n1, d1);
    unsigned s0 = (__float_as_uint(a0) ^ __float_as_uint(b0)) & 0x80000000u;
    unsigned s1 = (__float_as_uint(a1) ^ __float_as_uint(b1)) & 0x80000000u;
    r0 = __uint_as_float(__float_as_uint(r0) | s0);
    r1 = __uint_as_float(__float_as_uint(r1) | s1);
    return pk(r0, r1);
}

// ---------------------------------------------------------------------------
// Kernel 1: per-batch inclusive cumsum of delta_x[..., 2] plus init temp.
// ---------------------------------------------------------------------------
__global__ void scan_kernel(const float* __restrict__ delta_x) {
    __shared__ float ssum[512];
    const int b = blockIdx.x;
    const int t = threadIdx.x;
    const float* dx = delta_x + (size_t)b * SEQ * 6;

    const int s0 = t * 8;
    float v[8];
    float run = 0.0f;
#pragma unroll
    for (int k = 0; k < 8; k++) {
        run += dx[(s0 + k) * 6 + 2];
        v[k] = run;
    }
    ssum[t] = run;
    __syncthreads();

#pragma unroll
    for (int off = 1; off < 512; off <<= 1) {
        float x = ssum[t];
        float y = (t >= off) ? ssum[t - off] : 0.0f;
        __syncthreads();
        ssum[t] = x + y;
        __syncthreads();
    }

    const float init = dx[5];
    const float base = (t > 0 ? ssum[t - 1] : 0.0f) + init;

    float* tp = g_temp + (size_t)b * SEQ;
#pragma unroll
    for (int k = 0; k < 8; k++) tp[s0 + k] = base + v[k];
}

// ---------------------------------------------------------------------------
// Kernel 2: fused MLP, 2 positions per thread packed into f32x2 halves.
// Weights pre-doubled (w,w) in shared memory -> direct f32x2 operands.
// ---------------------------------------------------------------------------
__global__ void __launch_bounds__(128, 3)
msc_kernel(const float* __restrict__ h_prev, const float* __restrict__ delta_x,
           const float* __restrict__ Wa0, const float* __restrict__ ba0,
           const float* __restrict__ Wb0, const float* __restrict__ bb0,
           const float* __restrict__ Wa1, const float* __restrict__ ba1,
           const float* __restrict__ Wb1, const float* __restrict__ bb1,
           const float* __restrict__ W_alpha, const float* __restrict__ b_alpha,
           const float* __restrict__ W_beta,  const float* __restrict__ b_beta,
           const float* __restrict__ W_gamma, const float* __restrict__ b_gamma,
           const float* __restrict__ W_c,     const float* __restrict__ b_c,
           const float* __restrict__ W_out,
           float* __restrict__ out)
{
    __shared__ __align__(16) ull sWa0[9 * 32];    // (w,w) pairs, [i*32+j]
    __shared__ __align__(16) ull sWb0[9 * 32];
    __shared__ __align__(16) ull sWa1T[32 * 32];  // transposed [j*32+k]
    __shared__ __align__(16) ull sWb1T[32 * 32];
    __shared__ __align__(16) ull sWh[32 * 8];     // [i*8 + {a,b,g,c0..c4}]
    __shared__ ull sba0[32], sbb0[32], sba1[32], sbb1[32];
    __shared__ ull sbh[8];
    __shared__ float sWout[5];

    const int tid = threadIdx.x;

    for (int k = tid; k < 9 * 32; k += 128) {
        float w = Wa0[k]; sWa0[k] = pk(w, w);
        float v = Wb0[k]; sWb0[k] = pk(v, v);
    }
    for (int k = tid; k < 1024; k += 128) {
        int i = k >> 5, j = k & 31;
        float w = Wa1[k]; sWa1T[j * 32 + i] = pk(w, w);
        float v = Wb1[k]; sWb1T[j * 32 + i] = pk(v, v);
    }
    if (tid < 32) {
        sba0[tid] = pk(ba0[tid], ba0[tid]);
        sbb0[tid] = pk(bb0[tid], bb0[tid]);
        sba1[tid] = pk(ba1[tid], ba1[tid]);
        sbb1[tid] = pk(bb1[tid], bb1[tid]);
        float w;
        w = W_alpha[tid]; sWh[tid * 8 + 0] = pk(w, w);
        w = W_beta[tid];  sWh[tid * 8 + 1] = pk(w, w);
        w = W_gamma[tid]; sWh[tid * 8 + 2] = pk(w, w);
#pragma unroll
        for (int d = 0; d < 5; d++) { w = W_c[tid * 5 + d]; sWh[tid * 8 + 3 + d] = pk(w, w); }
    }
    if (tid == 0) {
        float w;
        w = b_alpha[0]; sbh[0] = pk(w, w);
        w = b_beta[0];  sbh[1] = pk(w, w);
        w = b_gamma[0]; sbh[2] = pk(w, w);
#pragma unroll
        for (int d = 0; d < 5; d++) { w = b_c[d]; sbh[3 + d] = pk(w, w); }
#pragma unroll
        for (int d = 0; d < 5; d++) sWout[d] = W_out[d];
    }
    __syncthreads();

    const int p0 = blockIdx.x * 256 + tid;
    const int p1 = p0 + 128;

    // ---- inputs (packed) ----
    const float* hp0 = h_prev + (size_t)p0 * 5;
    const float* hp1 = h_prev + (size_t)p1 * 5;
    const float* dx0 = delta_x + (size_t)p0 * 6;
    const float* dx1 = delta_x + (size_t)p1 * 6;

    ull l2[9];
#pragma unroll
    for (int d = 0; d < 5; d++) l2[d] = pk(hp0[d], hp1[d]);
    const float d00 = dx0[0], d10 = dx0[1], d20 = dx0[2];
    const float d01 = dx1[0], d11 = dx1[1], d21 = dx1[2];
    l2[5] = pk(g_temp[p0], g_temp[p1]);
    {
        float n0 = fmaxf(sqrtf(d00 * d00 + d10 * d10 + d20 * d20), 1e-7f);
        float n1 = fmaxf(sqrtf(d01 * d01 + d11 * d11 + d21 * d21), 1e-7f);
        float i0 = __fdividef(1.0f, n0);
        float i1 = __fdividef(1.0f, n1);
        l2[6] = pk(d00 * i0, d01 * i1);
        l2[7] = pk(d10 * i0, d11 * i1);
        l2[8] = pk(d20 * i0, d21 * i1);
    }

    // ---- layer 0 (two j-halves of 16 to bound register pressure) ----
    ull h[32];
#pragma unroll
    for (int half = 0; half < 2; half++) {
        ull aA[16], aB[16];
#pragma unroll
        for (int jj = 0; jj < 16; jj++) {
            aA[jj] = sba0[half * 16 + jj];
            aB[jj] = sbb0[half * 16 + jj];
        }
#pragma unroll
        for (int i = 0; i < 9; i++) {
            const ull li = l2[i];
            const ulonglong2* wA = (const ulonglong2*)(sWa0 + i * 32 + half * 16);
            const ulonglong2* wB = (const ulonglong2*)(sWb0 + i * 32 + half * 16);
#pragma unroll
            for (int q = 0; q < 8; q++) {
                ulonglong2 wa = wA[q];
                ulonglong2 wb = wB[q];
                aA[2 * q + 0] = fma2(li, wa.x, aA[2 * q + 0]);
                aA[2 * q + 1] = fma2(li, wa.y, aA[2 * q + 1]);
                aB[2 * q + 0] = fma2(li, wb.x, aB[2 * q + 0]);
                aB[2 * q + 1] = fma2(li, wb.y, aB[2 * q + 1]);
            }
        }
#pragma unroll
        for (int jj = 0; jj < 16; jj++)
            h[half * 16 + jj] = gtanh2(aA[jj], aB[jj]);
    }

    // ---- layer 1 fused with heads: h2[j] folded straight into acc8 ----
    ull acc8[8];
#pragma unroll
    for (int k = 0; k < 8; k++) acc8[k] = sbh[k];

    const ull zero2 = pk(0.0f, 0.0f);
#pragma unroll
    for (int j = 0; j < 32; j++) {
        ull va0 = sba1[j], va1 = zero2;
        ull vb0 = sbb1[j], vb1 = zero2;
        const ulonglong2* wa = (const ulonglong2*)(sWa1T + j * 32);
        const ulonglong2* wb = (const ulonglong2*)(sWb1T + j * 32);
#pragma unroll
        for (int q = 0; q < 16; q++) {
            ulonglong2 A = wa[q];
            ulonglong2 B = wb[q];
            va0 = fma2(h[2 * q + 0], A.x, va0);
            va1 = fma2(h[2 * q + 1], A.y, va1);
            vb0 = fma2(h[2 * q + 0], B.x, vb0);
            vb1 = fma2(h[2 * q + 1], B.y, vb1);
        }
        ull g = gtanh2(add2(va0, va1), add2(vb0, vb1));
        const ulonglong2* wh = (const ulonglong2*)(sWh + j * 8);
#pragma unroll
        for (int q = 0; q < 4; q++) {
            ulonglong2 W = wh[q];
            acc8[2 * q + 0] = fma2(g, W.x, acc8[2 * q + 0]);
            acc8[2 * q + 1] = fma2(g, W.y, acc8[2 * q + 1]);
        }
    }

    // ---- epilogue per position ----
    float xa0, xa1, xb0, xb1, xg0, xg1;
    upk(acc8[0], xa0, xa1);
    upk(acc8[1], xb0, xb1);
    upk(acc8[2], xg0, xg1);
    const float alpha0 = __expf(xa0), alpha1 = __expf(xa1);
    const float beta0  = __expf(xb0), beta1  = __expf(xb1);
    const float gamma0 = __expf(xg0), gamma1 = __expf(xg1);
    const float z0 = 1.0f - __expf(-(alpha0 * fabsf(d00) + beta0 * d10 + gamma0 * fabsf(d20)));
    const float z1 = 1.0f - __expf(-(alpha1 * fabsf(d01) + beta1 * d11 + gamma1 * fabsf(d21)));

    float sig0 = 0.0f, sig1 = 0.0f;
    float* o0 = out + (size_t)p0 * 5;
    float* o1 = out + (size_t)p1 * 5;
#pragma unroll
    for (int d = 0; d < 5; d++) {
        float c0v, c1v;
        upk(acc8[3 + d], c0v, c1v);
        c0v = fast_tanh(c0v);
        c1v = fast_tanh(c1v);
        float h0v, h1v;
        upk(l2[d], h0v, h1v);
        float hn0 = fmaf(z0, c0v - h0v, h0v);
        float hn1 = fmaf(z1, c1v - h1v, h1v);
        o0[d] = hn0;
        o1[d] = hn1;
        sig0 = fmaf(hn0, sWout[d], sig0);
        sig1 = fmaf(hn1, sWout[d], sig1);
    }
    out[(size_t)NPOS * 5 + p0] = sig0;
    out[(size_t)NPOS * 5 + p1] = sig1;
}

extern "C" void kernel_launch(void* const* d_in, const int* in_sizes, int n_in,
                              void* d_out, int out_size) {
    const float* h_prev  = (const float*)d_in[0];
    const float* delta_x = (const float*)d_in[1];
    const float* Wa0     = (const float*)d_in[2];
    const float* ba0     = (const float*)d_in[3];
    const float* Wb0     = (const float*)d_in[4];
    const float* bb0     = (const float*)d_in[5];
    const float* Wa1     = (const float*)d_in[6];
    const float* ba1     = (const float*)d_in[7];
    const float* Wb1     = (const float*)d_in[8];
    const float* bb1     = (const float*)d_in[9];
    const float* W_alpha = (const float*)d_in[10];
    const float* b_alpha = (const float*)d_in[11];
    const float* W_beta  = (const float*)d_in[12];
    const float* b_beta  = (const float*)d_in[13];
    const float* W_gamma = (const float*)d_in[14];
    const float* b_gamma = (const float*)d_in[15];
    const float* W_c     = (const float*)d_in[16];
    const float* b_c     = (const float*)d_in[17];
    const float* W_out   = (const float*)d_in[18];
    float* out = (float*)d_out;

    scan_kernel<<<BATCH, 512>>>(delta_x);
    msc_kernel<<<NPOS / 256, 128>>>(h_prev, delta_x,
                                    Wa0, ba0, Wb0, bb0,
                                    Wa1, ba1, Wb1, bb1,
                                    W_alpha, b_alpha, W_beta, b_beta,
                                    W_gamma, b_gamma, W_c, b_c, W_out,
                                    out);
}

// round 11
// speedup vs baseline: 1.2273x; 1.2273x over previous
#include <cuda_runtime.h>

#define BATCH 128
#define SEQ   4096
#define NPOS  (BATCH * SEQ)

// ---- constant-bank layout (floats) ----
#define OFF_WA0   0
#define OFF_WB0   288
#define OFF_WA1   576
#define OFF_WB1   1600
#define OFF_BA0   2624
#define OFF_BB0   2656
#define OFF_BA1   2688
#define OFF_BB1   2720
#define OFF_WAL   2752
#define OFF_WBE   2784
#define OFF_WGA   2816
#define OFF_WC    2848
#define OFF_BAL   3008
#define OFF_BBE   3009
#define OFF_BGA   3010
#define OFF_BC    3011
#define OFF_WOUT  3016
#define TOTALW    3021

__constant__ float cW[TOTALW];

// Staging + scan scratch (static __device__: no allocation).
__device__ float g_stage[TOTALW];
__device__ float g_temp[NPOS];

// Fused gated tanh: tanh(a)*tanh(b) = sign(a^b)*(1-ta)(1-tb)/((1+ta)(1+tb)),
// t = e^{-2|x|}. One divide per gate instead of two. Validated in R8 (rel_err 1.7e-7).
__device__ __forceinline__ float gtanh(float a, float b) {
    float ta = __expf(-2.0f * fabsf(a));
    float tb = __expf(-2.0f * fabsf(b));
    float n = (1.0f - ta) * (1.0f - tb);
    float d = (1.0f + ta) * (1.0f + tb);
    float r = __fdividef(n, d);
    unsigned s = (__float_as_uint(a) ^ __float_as_uint(b)) & 0x80000000u;
    return __uint_as_float(__float_as_uint(r) | s);
}

__device__ __forceinline__ float fast_tanh(float x) {
    float t = __expf(-2.0f * fabsf(x));
    float r = __fdividef(1.0f - t, 1.0f + t);
    return copysignf(r, x);
}

// ---------------------------------------------------------------------------
// Kernel 0: gather all weights into one contiguous staging buffer.
// ---------------------------------------------------------------------------
__global__ void gather_kernel(const float* __restrict__ Wa0, const float* __restrict__ ba0,
                              const float* __restrict__ Wb0, const float* __restrict__ bb0,
                              const float* __restrict__ Wa1, const float* __restrict__ ba1,
                              const float* __restrict__ Wb1, const float* __restrict__ bb1,
                              const float* __restrict__ W_alpha, const float* __restrict__ b_alpha,
                              const float* __restrict__ W_beta,  const float* __restrict__ b_beta,
                              const float* __restrict__ W_gamma, const float* __restrict__ b_gamma,
                              const float* __restrict__ W_c,     const float* __restrict__ b_c,
                              const float* __restrict__ W_out) {
    const int t = threadIdx.x;
    for (int i = t; i < 288; i += 256)  { g_stage[OFF_WA0 + i] = Wa0[i]; g_stage[OFF_WB0 + i] = Wb0[i]; }
    for (int i = t; i < 1024; i += 256) { g_stage[OFF_WA1 + i] = Wa1[i]; g_stage[OFF_WB1 + i] = Wb1[i]; }
    if (t < 32) {
        g_stage[OFF_BA0 + t] = ba0[t];
        g_stage[OFF_BB0 + t] = bb0[t];
        g_stage[OFF_BA1 + t] = ba1[t];
        g_stage[OFF_BB1 + t] = bb1[t];
        g_stage[OFF_WAL + t] = W_alpha[t];
        g_stage[OFF_WBE + t] = W_beta[t];
        g_stage[OFF_WGA + t] = W_gamma[t];
    }
    for (int i = t; i < 160; i += 256) g_stage[OFF_WC + i] = W_c[i];
    if (t == 0) {
        g_stage[OFF_BAL] = b_alpha[0];
        g_stage[OFF_BBE] = b_beta[0];
        g_stage[OFF_BGA] = b_gamma[0];
        for (int d = 0; d < 5; d++) g_stage[OFF_BC + d] = b_c[d];
        for (int d = 0; d < 5; d++) g_stage[OFF_WOUT + d] = W_out[d];
    }
}

// ---------------------------------------------------------------------------
// Kernel 1: per-batch inclusive cumsum of delta_x[..., 2] plus init temp.
// ---------------------------------------------------------------------------
__global__ void scan_kernel(const float* __restrict__ delta_x) {
    __shared__ float ssum[512];
    const int b = blockIdx.x;
    const int t = threadIdx.x;
    const float* dx = delta_x + (size_t)b * SEQ * 6;

    const int s0 = t * 8;
    float v[8];
    float run = 0.0f;
#pragma unroll
    for (int k = 0; k < 8; k++) {
        run += dx[(s0 + k) * 6 + 2];
        v[k] = run;
    }
    ssum[t] = run;
    __syncthreads();

#pragma unroll
    for (int off = 1; off < 512; off <<= 1) {
        float x = ssum[t];
        float y = (t >= off) ? ssum[t - off] : 0.0f;
        __syncthreads();
        ssum[t] = x + y;
        __syncthreads();
    }

    const float init = dx[5];
    const float base = (t > 0 ? ssum[t - 1] : 0.0f) + init;

    float* tp = g_temp + (size_t)b * SEQ;
#pragma unroll
    for (int k = 0; k < 8; k++) tp[s0 + k] = base + v[k];
}

// ---------------------------------------------------------------------------
// Kernel 2: fused per-position MLP, weights in __constant__ (uniform port —
// no shared memory, no LDS crossbar traffic, no __syncthreads).
// ---------------------------------------------------------------------------
__global__ void __launch_bounds__(256, 2)
msc_kernel(const float* __restrict__ h_prev, const float* __restrict__ delta_x,
           float* __restrict__ out)
{
    const int idx = blockIdx.x * 256 + threadIdx.x;

    // ---- inputs ----
    const float* hp = h_prev + (size_t)idx * 5;
    const float* dx = delta_x + (size_t)idx * 6;
    float l[9];
#pragma unroll
    for (int d = 0; d < 5; d++) l[d] = hp[d];
    const float d0 = dx[0], d1 = dx[1], d2 = dx[2];
    l[5] = g_temp[idx];
    {
        float nrm = fmaxf(sqrtf(d0 * d0 + d1 * d1 + d2 * d2), 1e-7f);
        float inv = __fdividef(1.0f, nrm);
        l[6] = d0 * inv; l[7] = d1 * inv; l[8] = d2 * inv;
    }

    // ---- layer 0: h = tanh(l@Wa0+ba0)*tanh(l@Wb0+bb0), two j-halves of 16 ----
    float h[32];
#pragma unroll
    for (int half = 0; half < 2; half++) {
        float aA[16], aB[16];
#pragma unroll
        for (int jj = 0; jj < 16; jj++) {
            aA[jj] = cW[OFF_BA0 + half * 16 + jj];
            aB[jj] = cW[OFF_BB0 + half * 16 + jj];
        }
#pragma unroll
        for (int i = 0; i < 9; i++) {
            const float li = l[i];
#pragma unroll
            for (int jj = 0; jj < 16; jj++) {
                aA[jj] = fmaf(li, cW[OFF_WA0 + i * 32 + half * 16 + jj], aA[jj]);
                aB[jj] = fmaf(li, cW[OFF_WB0 + i * 32 + half * 16 + jj], aB[jj]);
            }
        }
#pragma unroll
        for (int jj = 0; jj < 16; jj++)
            h[half * 16 + jj] = gtanh(aA[jj], aB[jj]);
    }

    // ---- heads accumulators (alpha, beta, gamma, c0..c4) ----
    float acc8[8];
    acc8[0] = cW[OFF_BAL];
    acc8[1] = cW[OFF_BBE];
    acc8[2] = cW[OFF_BGA];
#pragma unroll
    for (int d = 0; d < 5; d++) acc8[3 + d] = cW[OFF_BC + d];

    // ---- layer 1 + heads, two j-halves of 16, k-outer (natural layout) ----
#pragma unroll
    for (int half = 0; half < 2; half++) {
        float vA[16], vB[16];
#pragma unroll
        for (int jj = 0; jj < 16; jj++) {
            vA[jj] = cW[OFF_BA1 + half * 16 + jj];
            vB[jj] = cW[OFF_BB1 + half * 16 + jj];
        }
#pragma unroll
        for (int k = 0; k < 32; k++) {
            const float hk = h[k];
#pragma unroll
            for (int jj = 0; jj < 16; jj++) {
                vA[jj] = fmaf(hk, cW[OFF_WA1 + k * 32 + half * 16 + jj], vA[jj]);
                vB[jj] = fmaf(hk, cW[OFF_WB1 + k * 32 + half * 16 + jj], vB[jj]);
            }
        }
#pragma unroll
        for (int jj = 0; jj < 16; jj++) {
            const int j = half * 16 + jj;
            const float g = gtanh(vA[jj], vB[jj]);
            acc8[0] = fmaf(g, cW[OFF_WAL + j], acc8[0]);
            acc8[1] = fmaf(g, cW[OFF_WBE + j], acc8[1]);
            acc8[2] = fmaf(g, cW[OFF_WGA + j], acc8[2]);
#pragma unroll
            for (int d = 0; d < 5; d++)
                acc8[3 + d] = fmaf(g, cW[OFF_WC + j * 5 + d], acc8[3 + d]);
        }
    }

    // ---- epilogue ----
    const float alpha = __expf(acc8[0]);
    const float beta  = __expf(acc8[1]);
    const float gamma = __expf(acc8[2]);
    const float zarg  = alpha * fabsf(d0) + beta * d1 + gamma * fabsf(d2);
    const float z     = 1.0f - __expf(-zarg);

    float sigma = 0.0f;
    float* oh = out + (size_t)idx * 5;
#pragma unroll
    for (int d = 0; d < 5; d++) {
        float c  = fast_tanh(acc8[3 + d]);
        float hn = fmaf(z, c - l[d], l[d]);  // (1-z)*h_prev + z*c
        oh[d] = hn;
        sigma = fmaf(hn, cW[OFF_WOUT + d], sigma);
    }
    out[(size_t)NPOS * 5 + idx] = sigma;
}

extern "C" void kernel_launch(void* const* d_in, const int* in_sizes, int n_in,
                              void* d_out, int out_size) {
    const float* h_prev  = (const float*)d_in[0];
    const float* delta_x = (const float*)d_in[1];
    float* out = (float*)d_out;

    scan_kernel<<<BATCH, 512>>>(delta_x);
    gather_kernel<<<1, 256>>>((const float*)d_in[2],  (const float*)d_in[3],
                              (const float*)d_in[4],  (const float*)d_in[5],
                              (const float*)d_in[6],  (const float*)d_in[7],
                              (const float*)d_in[8],  (const float*)d_in[9],
                              (const float*)d_in[10], (const float*)d_in[11],
                              (const float*)d_in[12], (const float*)d_in[13],
                              (const float*)d_in[14], (const float*)d_in[15],
                              (const float*)d_in[16], (const float*)d_in[17],
                              (const float*)d_in[18]);

    void* stage_ptr = nullptr;
    cudaGetSymbolAddress(&stage_ptr, g_stage);
    cudaMemcpyToSymbolAsync(cW, stage_ptr, TOTALW * sizeof(float), 0,
                            cudaMemcpyDeviceToDevice, 0);

    msc_kernel<<<NPOS / 256, 256>>>(h_prev, delta_x, out);
}

// round 17
// speedup vs baseline: 1.2444x; 1.0140x over previous
#include <cuda_runtime.h>

#define BATCH 128
#define SEQ   4096
#define NPOS  (BATCH * SEQ)

// ---- constant-bank layout (floats) ----
#define OFF_WA0   0
#define OFF_WB0   288
#define OFF_WA1   576
#define OFF_WB1   1600
#define OFF_BA0   2624
#define OFF_BB0   2656
#define OFF_BA1   2688
#define OFF_BB1   2720
#define OFF_WH    2752   // [32][8]: alpha,beta,gamma,c0..c4 per hidden j (32B stride)
#define OFF_BH    3008   // alpha,beta,gamma,c0..c4 biases
#define OFF_WOUT  3016
#define TOTALW    3021

__constant__ float cW[TOTALW];

// Staging + scan scratch (static __device__: no allocation).
__device__ float g_stage[TOTALW];
__device__ float g_temp[NPOS];

// Fused gated tanh: tanh(a)*tanh(b) = sign(a^b)*(1-ta)(1-tb)/((1+ta)(1+tb)),
// t = e^{-2|x|}. One divide per gate instead of two. Validated (rel_err ~1.7e-7).
__device__ __forceinline__ float gtanh(float a, float b) {
    float ta = __expf(-2.0f * fabsf(a));
    float tb = __expf(-2.0f * fabsf(b));
    float n = (1.0f - ta) * (1.0f - tb);
    float d = (1.0f + ta) * (1.0f + tb);
    float r = __fdividef(n, d);
    unsigned s = (__float_as_uint(a) ^ __float_as_uint(b)) & 0x80000000u;
    return __uint_as_float(__float_as_uint(r) | s);
}

__device__ __forceinline__ float fast_tanh(float x) {
    float t = __expf(-2.0f * fabsf(x));
    float r = __fdividef(1.0f - t, 1.0f + t);
    return copysignf(r, x);
}

// ---------------------------------------------------------------------------
// Kernel 0: gather all weights into one contiguous staging buffer.
// ---------------------------------------------------------------------------
__global__ void gather_kernel(const float* __restrict__ Wa0, const float* __restrict__ ba0,
                              const float* __restrict__ Wb0, const float* __restrict__ bb0,
                              const float* __restrict__ Wa1, const float* __restrict__ ba1,
                              const float* __restrict__ Wb1, const float* __restrict__ bb1,
                              const float* __restrict__ W_alpha, const float* __restrict__ b_alpha,
                              const float* __restrict__ W_beta,  const float* __restrict__ b_beta,
                              const float* __restrict__ W_gamma, const float* __restrict__ b_gamma,
                              const float* __restrict__ W_c,     const float* __restrict__ b_c,
                              const float* __restrict__ W_out) {
    const int t = threadIdx.x;
    for (int i = t; i < 288; i += 256)  { g_stage[OFF_WA0 + i] = Wa0[i]; g_stage[OFF_WB0 + i] = Wb0[i]; }
    for (int i = t; i < 1024; i += 256) { g_stage[OFF_WA1 + i] = Wa1[i]; g_stage[OFF_WB1 + i] = Wb1[i]; }
    if (t < 32) {
        g_stage[OFF_BA0 + t] = ba0[t];
        g_stage[OFF_BB0 + t] = bb0[t];
        g_stage[OFF_BA1 + t] = ba1[t];
        g_stage[OFF_BB1 + t] = bb1[t];
        // head weights packed per hidden unit: 32B stride
        g_stage[OFF_WH + t * 8 + 0] = W_alpha[t];
        g_stage[OFF_WH + t * 8 + 1] = W_beta[t];
        g_stage[OFF_WH + t * 8 + 2] = W_gamma[t];
        for (int d = 0; d < 5; d++) g_stage[OFF_WH + t * 8 + 3 + d] = W_c[t * 5 + d];
    }
    if (t == 0) {
        g_stage[OFF_BH + 0] = b_alpha[0];
        g_stage[OFF_BH + 1] = b_beta[0];
        g_stage[OFF_BH + 2] = b_gamma[0];
        for (int d = 0; d < 5; d++) g_stage[OFF_BH + 3 + d] = b_c[d];
        for (int d = 0; d < 5; d++) g_stage[OFF_WOUT + d] = W_out[d];
    }
}

// ---------------------------------------------------------------------------
// Kernel 1: coalesced per-batch inclusive cumsum of delta_x[..., 2].
// Chunks of 512 positions staged in smem (coalesced), shfl warp scan,
// cross-warp scan, register carry. Traffic 12.6 MB instead of ~100 MB.
// ---------------------------------------------------------------------------
__global__ void scan_kernel(const float* __restrict__ delta_x) {
    __shared__ float sbuf[512 * 6];
    __shared__ float wsum[16];
    const int b = blockIdx.x;
    const int t = threadIdx.x;
    const int lane = t & 31;
    const int wid = t >> 5;
    const float* base = delta_x + (size_t)b * SEQ * 6;
    const float init = base[5];  // delta_x[b, 0, 5]
    float carry = init;
    float* tp = g_temp + (size_t)b * SEQ;

    for (int c = 0; c < 8; c++) {
        const float* cb = base + c * 512 * 6;
        // coalesced: 6 strips of 512 consecutive floats
#pragma unroll
        for (int i = 0; i < 6; i++) sbuf[i * 512 + t] = cb[i * 512 + t];
        __syncthreads();

        float x = sbuf[t * 6 + 2];  // channel 2 of position t in chunk
        // inclusive warp scan
#pragma unroll
        for (int off = 1; off < 32; off <<= 1) {
            float y = __shfl_up_sync(0xffffffffu, x, off);
            if (lane >= off) x += y;
        }
        if (lane == 31) wsum[wid] = x;
        __syncthreads();

        // scan the 16 warp sums in warp 0
        if (t < 32) {
            float s = (lane < 16) ? wsum[lane] : 0.0f;
#pragma unroll
            for (int off = 1; off < 16; off <<= 1) {
                float y = __shfl_up_sync(0xffffffffu, s, off);
                if (lane >= off) s += y;
            }
            if (lane < 16) wsum[lane] = s;
        }
        __syncthreads();

        const float pre = (wid > 0) ? wsum[wid - 1] : 0.0f;
        tp[c * 512 + t] = carry + pre + x;
        carry += wsum[15];  // block total of this chunk (every thread tracks carry)
        __syncthreads();    // protect sbuf/wsum before next chunk overwrites
    }
}

// ---------------------------------------------------------------------------
// Kernel 2: fused per-position MLP, weights in __constant__ (uniform port —
// no shared memory, no LDS crossbar traffic, no __syncthreads).
// ---------------------------------------------------------------------------
__global__ void __launch_bounds__(256, 2)
msc_kernel(const float* __restrict__ h_prev, const float* __restrict__ delta_x,
           float* __restrict__ out)
{
    const int idx = blockIdx.x * 256 + threadIdx.x;

    // ---- inputs ----
    const float* hp = h_prev + (size_t)idx * 5;
    const float* dx = delta_x + (size_t)idx * 6;
    float l[9];
#pragma unroll
    for (int d = 0; d < 5; d++) l[d] = hp[d];
    const float d0 = dx[0], d1 = dx[1], d2 = dx[2];
    l[5] = g_temp[idx];
    {
        float nrm = fmaxf(sqrtf(d0 * d0 + d1 * d1 + d2 * d2), 1e-7f);
        float inv = __fdividef(1.0f, nrm);
        l[6] = d0 * inv; l[7] = d1 * inv; l[8] = d2 * inv;
    }

    // ---- layer 0: h = tanh(l@Wa0+ba0)*tanh(l@Wb0+bb0), two j-halves of 16 ----
    float h[32];
#pragma unroll
    for (int half = 0; half < 2; half++) {
        float aA[16], aB[16];
#pragma unroll
        for (int jj = 0; jj < 16; jj++) {
            aA[jj] = cW[OFF_BA0 + half * 16 + jj];
            aB[jj] = cW[OFF_BB0 + half * 16 + jj];
        }
#pragma unroll
        for (int i = 0; i < 9; i++) {
            const float li = l[i];
#pragma unroll
            for (int jj = 0; jj < 16; jj++) {
                aA[jj] = fmaf(li, cW[OFF_WA0 + i * 32 + half * 16 + jj], aA[jj]);
                aB[jj] = fmaf(li, cW[OFF_WB0 + i * 32 + half * 16 + jj], aB[jj]);
            }
        }
#pragma unroll
        for (int jj = 0; jj < 16; jj++)
            h[half * 16 + jj] = gtanh(aA[jj], aB[jj]);
    }

    // ---- heads accumulators (alpha, beta, gamma, c0..c4) ----
    float acc8[8];
#pragma unroll
    for (int k = 0; k < 8; k++) acc8[k] = cW[OFF_BH + k];

    // ---- layer 1 + heads, two j-halves of 16, k-outer (natural layout) ----
#pragma unroll
    for (int half = 0; half < 2; half++) {
        float vA[16], vB[16];
#pragma unroll
        for (int jj = 0; jj < 16; jj++) {
            vA[jj] = cW[OFF_BA1 + half * 16 + jj];
            vB[jj] = cW[OFF_BB1 + half * 16 + jj];
        }
#pragma unroll
        for (int k = 0; k < 32; k++) {
            const float hk = h[k];
#pragma unroll
            for (int jj = 0; jj < 16; jj++) {
                vA[jj] = fmaf(hk, cW[OFF_WA1 + k * 32 + half * 16 + jj], vA[jj]);
                vB[jj] = fmaf(hk, cW[OFF_WB1 + k * 32 + half * 16 + jj], vB[jj]);
            }
        }
#pragma unroll
        for (int jj = 0; jj < 16; jj++) {
            const int j = half * 16 + jj;
            const float g = gtanh(vA[jj], vB[jj]);
#pragma unroll
            for (int k = 0; k < 8; k++)
                acc8[k] = fmaf(g, cW[OFF_WH + j * 8 + k], acc8[k]);
        }
    }

    // ---- epilogue ----
    const float alpha = __expf(acc8[0]);
    const float beta  = __expf(acc8[1]);
    const float gamma = __expf(acc8[2]);
    const float zarg  = alpha * fabsf(d0) + beta * d1 + gamma * fabsf(d2);
    const float z     = 1.0f - __expf(-zarg);

    float sigma = 0.0f;
    float* oh = out + (size_t)idx * 5;
#pragma unroll
    for (int d = 0; d < 5; d++) {
        float c  = fast_tanh(acc8[3 + d]);
        float hn = fmaf(z, c - l[d], l[d]);  // (1-z)*h_prev + z*c
        oh[d] = hn;
        sigma = fmaf(hn, cW[OFF_WOUT + d], sigma);
    }
    out[(size_t)NPOS * 5 + idx] = sigma;
}

extern "C" void kernel_launch(void* const* d_in, const int* in_sizes, int n_in,
                              void* d_out, int out_size) {
    const float* h_prev  = (const float*)d_in[0];
    const float* delta_x = (const float*)d_in[1];
    float* out = (float*)d_out;

    scan_kernel<<<BATCH, 512>>>(delta_x);
    gather_kernel<<<1, 256>>>((const float*)d_in[2],  (const float*)d_in[3],
                              (const float*)d_in[4],  (const float*)d_in[5],
                              (const float*)d_in[6],  (const float*)d_in[7],
                              (const float*)d_in[8],  (const float*)d_in[9],
                              (const float*)d_in[10], (const float*)d_in[11],
                              (const float*)d_in[12], (const float*)d_in[13],
                              (const float*)d_in[14], (const float*)d_in[15],
                              (const float*)d_in[16], (const float*)d_in[17],
                              (const float*)d_in[18]);

    void* stage_ptr = nullptr;
    cudaGetSymbolAddress(&stage_ptr, g_stage);
    cudaMemcpyToSymbolAsync(cW, stage_ptr, TOTALW * sizeof(float), 0,
                            cudaMemcpyDeviceToDevice, 0);

    msc_kernel<<<NPOS / 256, 256>>>(h_prev, delta_x, out);
}